// round 12
// baseline (speedup 1.0000x reference)
#include <cuda_runtime.h>
#include <cuda_fp16.h>
#include <cstdint>
#include <cstddef>

#define NHEAD 8
#define HID 512
#define DK 64
#define SEQ 1024
#define BATCH 4
#define TOK 4096
#define WIN 34
#define KDIM 512

#define BK 64
#define OFF_B 16384
#define STAGE_B 32768                  // A | B
#define GSMEM (3 * STAGE_B)            // 98304, 3-stage pipeline
#define NCTA 296

// ---------------- scratch ----------------
__device__ float g_st  [2ull * TOK * HID];
__device__ float g_y   [2ull * TOK * HID];
__device__ __half g_qkv_h [2ull * TOK * 3 * HID];
__device__ __half g_act_h [2ull * TOK * HID];
__device__ __half g_attn_h[2ull * TOK * HID];
__device__ __half g_yh    [2ull * TOK * HID];
__device__ __half g_y2h   [2ull * TOK * HID];
__device__ __half g_wqkv  [4194304];
__device__ __half g_whw   [4194304];

// ---------------- helpers ----------------
__device__ __forceinline__ uint32_t s2u(const void* p) {
    uint32_t a;
    asm("{ .reg .u64 t; cvta.to.shared.u64 t, %1; cvt.u32.u64 %0, t; }" : "=r"(a) : "l"(p));
    return a;
}
__device__ __forceinline__ void cpasync16(uint32_t dst, const void* src) {
    asm volatile("cp.async.cg.shared.global [%0], [%1], 16;" :: "r"(dst), "l"(src));
}
__device__ __forceinline__ void ldmx4(uint32_t* d, uint32_t a) {
    asm volatile("ldmatrix.sync.aligned.m8n8.x4.shared.b16 {%0,%1,%2,%3}, [%4];"
        : "=r"(d[0]), "=r"(d[1]), "=r"(d[2]), "=r"(d[3]) : "r"(a));
}
__device__ __forceinline__ void mma16816(float* c, const uint32_t* a, const uint32_t* b) {
    asm volatile("mma.sync.aligned.m16n8k16.row.col.f32.f16.f16.f32 "
        "{%0,%1,%2,%3}, {%4,%5,%6,%7}, {%8,%9}, {%0,%1,%2,%3};"
        : "+f"(c[0]), "+f"(c[1]), "+f"(c[2]), "+f"(c[3])
        : "r"(a[0]), "r"(a[1]), "r"(a[2]), "r"(a[3]), "r"(b[0]), "r"(b[1]));
}
__device__ __forceinline__ uint32_t pack_h2(float x, float y) {
    __half2 t = __floats2half2_rn(x, y);
    return *(uint32_t*)&t;
}

// ---------------- prep (merged): weight conversion + activation init ----------
__global__ void prep_all(const float* __restrict__ qkvw, const float* __restrict__ hww,
                         const float* __restrict__ in,
                         __half* __restrict__ dq, __half* __restrict__ dh)
{
    const size_t bi = blockIdx.x;
    if (bi < 4096) {
        const size_t i = bi * blockDim.x + threadIdx.x;
        float4 v = ((const float4*)qkvw)[i];
        *(uint2*)(dq + 4 * i) = make_uint2(pack_h2(v.x, v.y), pack_h2(v.z, v.w));
    } else if (bi < 8192) {
        const size_t idx = (bi - 4096) * blockDim.x + threadIdx.x;
        const size_t m   = idx >> 17;
        const size_t rem = idx & 131071;
        const int    r   = (int)(rem >> 7);
        const size_t c4  = rem & 127;
        const int dr = (r < 512) ? (2 * r) : (2 * (r - 512) + 1);
        float4 v = ((const float4*)hww)[idx];
        const size_t d = (m << 17) + (size_t)dr * 128 + c4;
        *(uint2*)(dh + 4 * d) = make_uint2(pack_h2(v.x, v.y), pack_h2(v.z, v.w));
    } else {
        const size_t idx = (bi - 8192) * blockDim.x + threadIdx.x;
        const float4 v = *(const float4*)(in + idx * 4);
        const uint2 p = make_uint2(pack_h2(v.x, v.y), pack_h2(v.z, v.w));
        *(uint2*)&g_act_h[idx * 4] = p;
        *(uint2*)&g_act_h[(size_t)TOK * HID + idx * 4] = p;
    }
}

// ---------------- persistent fused HMMA GEMM -------------------------------
// mode<=1: C fp32 (if C) and/or fp16 Sh (if Sh) | mode 2: highway mid | mode 3: final
__global__ __launch_bounds__(256, 2)
void gemm_fused(const __half* __restrict__ A, const __half* __restrict__ B,
                const float* __restrict__ bias, float* __restrict__ C,
                __half* __restrict__ Sh,
                float* __restrict__ Yv, float* __restrict__ St, float* __restrict__ Out,
                int N, size_t sB, size_t sbias, size_t sC, int mode, int add_res,
                int ntiles)
{
    extern __shared__ char smem[];
    const uint32_t sbase = s2u(smem);
    const int tid = threadIdx.x, lane = tid & 31, wid = tid >> 5;
    const int wm = wid & 1, wn = wid >> 1;

    const int bx = (int)blockIdx.x;
    const int nt = (bx < ntiles) ? ((ntiles - 1 - bx) / (int)gridDim.x + 1) : 0;
    if (nt == 0) return;
    const int total = nt * 8;

    const int r  = tid >> 1;
    const int c0 = (tid & 1) * 4;
    const uint32_t r7 = (uint32_t)(r & 7);
    uint32_t swz[4];
#pragma unroll
    for (int u = 0; u < 4; u++)
        swz[u] = (uint32_t)r * 128 + ((((uint32_t)(c0 + u)) ^ r7) << 4);

    const int m8 = lane >> 3, l7 = lane & 7;
    const uint32_t a_row = (uint32_t)(wm * 64 + (m8 & 1) * 8 + l7) * 128;
    const uint32_t b_row = (uint32_t)(wn * 32 + (m8 >> 1) * 8 + l7) * 128;
    uint32_t acol[4], bcol[4];
#pragma unroll
    for (int kk = 0; kk < 4; kk++) {
        acol[kk] = ((uint32_t)(kk * 2 + (m8 >> 1)) ^ (uint32_t)l7) << 4;
        bcol[kk] = ((uint32_t)(kk * 2 + (m8 & 1)) ^ (uint32_t)l7) << 4;
    }

    float acc[4][4][4];
#pragma unroll
    for (int i = 0; i < 4; i++)
#pragma unroll
        for (int j = 0; j < 4; j++)
#pragma unroll
            for (int k = 0; k < 4; k++) acc[i][j][k] = 0.f;

#define LOAD_G(g) do {                                                             \
        const int _t = bx + ((g) >> 3) * (int)gridDim.x;                           \
        const int _dir = _t & 1, _u = _t >> 1;                                     \
        const int _bm = (_u & 31) * 128, _bn = (_u >> 5) * 128;                    \
        const int _ke = ((g) & 7) * BK + c0 * 8;                                   \
        const __half* _Ap = A + (size_t)_dir * (TOK * KDIM)                        \
                              + (size_t)(_bm + r) * KDIM + _ke;                    \
        const __half* _Bp = B + (size_t)_dir * sB + (size_t)(_bn + r) * KDIM + _ke;\
        const uint32_t _sb = sbase + (uint32_t)((g) % 3) * STAGE_B;                \
        cpasync16(_sb + swz[0],         _Ap);                                      \
        cpasync16(_sb + swz[1],         _Ap + 8);                                  \
        cpasync16(_sb + swz[2],         _Ap + 16);                                 \
        cpasync16(_sb + swz[3],         _Ap + 24);                                 \
        cpasync16(_sb + OFF_B + swz[0], _Bp);                                      \
        cpasync16(_sb + OFF_B + swz[1], _Bp + 8);                                  \
        cpasync16(_sb + OFF_B + swz[2], _Bp + 16);                                 \
        cpasync16(_sb + OFF_B + swz[3], _Bp + 24);                                 \
        asm volatile("cp.async.commit_group;" ::: "memory");                       \
    } while (0)

    LOAD_G(0);
    LOAD_G(1);

    const int gr = lane >> 2, gc = (lane & 3) * 2;

#pragma unroll 1
    for (int g = 0; g < total; g++) {
        if (g < total - 1) asm volatile("cp.async.wait_group 1;" ::: "memory");
        else               asm volatile("cp.async.wait_group 0;" ::: "memory");
        __syncthreads();
        if (g + 2 < total) LOAD_G(g + 2);

        const uint32_t sb = sbase + (uint32_t)(g % 3) * STAGE_B;
#pragma unroll
        for (int kk = 0; kk < 4; kk++) {
            uint32_t a[4][4], b[2][4];
#pragma unroll
            for (int nj = 0; nj < 2; nj++)
                ldmx4(b[nj], sb + OFF_B + b_row + nj * 2048 + bcol[kk]);
#pragma unroll
            for (int mi = 0; mi < 4; mi++)
                ldmx4(a[mi], sb + a_row + mi * 2048 + acol[kk]);
#pragma unroll
            for (int mi = 0; mi < 4; mi++)
#pragma unroll
                for (int ni = 0; ni < 4; ni++)
                    mma16816(acc[mi][ni], a[mi], &b[ni >> 1][(ni & 1) * 2]);
        }

        if ((g & 7) == 7) {
            const int t = bx + (g >> 3) * (int)gridDim.x;
            const int dir = t & 1, u = t >> 1;
            const int bm = (u & 31) * 128, bn = (u >> 5) * 128;
            const float* bs = bias + (size_t)dir * sbias;

            if (mode <= 1) {
                float* Cp = C ? (C + (size_t)dir * sC) : nullptr;
                __half* SH = Sh ? (Sh + (size_t)dir * sC) : nullptr;
#pragma unroll
                for (int mi = 0; mi < 4; mi++) {
#pragma unroll
                    for (int ni = 0; ni < 4; ni++) {
                        const int row0 = bm + wm * 64 + mi * 16 + gr;
                        const int col  = bn + wn * 32 + ni * 8 + gc;
                        const float b0 = bs[col], b1 = bs[col + 1];
                        const float v00 = acc[mi][ni][0] + b0, v01 = acc[mi][ni][1] + b1;
                        const float v10 = acc[mi][ni][2] + b0, v11 = acc[mi][ni][3] + b1;
                        if (Cp) {
                            *(float2*)&Cp[(size_t)row0 * N + col]       = make_float2(v00, v01);
                            *(float2*)&Cp[(size_t)(row0 + 8) * N + col] = make_float2(v10, v11);
                        }
                        if (SH) {
                            *(uint32_t*)&SH[(size_t)row0 * N + col]       = pack_h2(v00, v01);
                            *(uint32_t*)&SH[(size_t)(row0 + 8) * N + col] = pack_h2(v10, v11);
                        }
                    }
                }
            } else {
                float* Y = Yv + (size_t)dir * TOK * HID;
                float* S = St ? (St + (size_t)dir * TOK * HID) : nullptr;
                __half* SH = Sh + (size_t)dir * TOK * HID;
#pragma unroll
                for (int mi = 0; mi < 4; mi++) {
#pragma unroll
                    for (int ni = 0; ni < 4; ni++) {
                        const int row0 = bm + wm * 64 + mi * 16 + gr;
                        const int col  = bn + wn * 32 + ni * 8 + gc;
                        const int j    = col >> 1;
                        const float bnl = bs[j], bgt = bs[j + HID];
#pragma unroll
                        for (int rr = 0; rr < 2; rr++) {
                            const int row = row0 + rr * 8;
                            const float n = acc[mi][ni][rr * 2]     + bnl;
                            const float gg = acc[mi][ni][rr * 2 + 1] + bgt;
                            const size_t o = (size_t)row * HID + j;
                            const float yo = Y[o];
                            const float s = 1.f / (1.f + __expf(-gg));
                            float v = s * yo + (1.f - s) * fmaxf(n, 0.f);
                            if (mode == 2) {
                                Y[o] = v;
                            } else {
                                if (add_res) v += S[o];
                                S[o] = v;
                                Out[(size_t)row * (2 * HID) + (size_t)dir * HID + j] = v;
                            }
                            SH[o] = __float2half(v);
                        }
                    }
                }
            }
#pragma unroll
            for (int i = 0; i < 4; i++)
#pragma unroll
                for (int j = 0; j < 4; j++)
#pragma unroll
                    for (int k = 0; k < 4; k++) acc[i][j][k] = 0.f;
        }
    }
#undef LOAD_G
}

// ---------------- banded local attention v6 (fp16 qkv input) -----------------
// Same structure as v5; global loads are __half (uint4 = 8 elems), converted to
// fp32 in smem. Math identical to v5 modulo fp16 input rounding.
#define ATT_SMEM (17384 * 4)
__global__ void attn_v6(const float* __restrict__ rel_l)
{
    extern __shared__ float sm[];
    float* Ks = sm;               // [64][100] transposed K: d-major
    float* Vs = sm + 6400;        // [97][68]
    float* qs = sm + 12996;       // [64][68]
    float* sbias = sm + 17348;    // [34]

    const int dir = blockIdx.z;
    const int bh = blockIdx.y;
    const int b = bh >> 3, h = bh & 7;
    const int q0 = blockIdx.x * 64;
    const int tid = threadIdx.x, w = tid >> 5, lane = tid & 31;
    const int W0 = (dir == 0) ? (q0 - 33) : q0;

    const __half* base = g_qkv_h + (size_t)dir * TOK * (3 * HID)
                                 + (size_t)(b * SEQ) * (3 * HID) + h * DK;

    if (tid < WIN)
        sbias[tid] = rel_l[((size_t)dir * NHEAD + h) * WIN + tid];

    // load q tile: 64 rows x 8 uint4 (8 halves each)
    for (int idx = tid; idx < 64 * 8; idx += 256) {
        const int row = idx >> 3, dq = (idx & 7) * 8;
        const uint4 raw = *(const uint4*)(base + (size_t)(q0 + row) * 1536 + dq);
        const __half2* hp = (const __half2*)&raw;
        float* qp = qs + row * 68 + dq;
#pragma unroll
        for (int k = 0; k < 4; k++) {
            const float2 f = __half22float2(hp[k]);
            qp[2 * k] = f.x; qp[2 * k + 1] = f.y;
        }
    }
    // load K (transposed) and V window: 97 rows x 8 uint4 each
    for (int idx = tid; idx < 97 * 8; idx += 256) {
        const int jl = idx >> 3, dq = (idx & 7) * 8;
        const int j = W0 + jl;
        float kf[8] = {0, 0, 0, 0, 0, 0, 0, 0};
        float vf[8] = {0, 0, 0, 0, 0, 0, 0, 0};
        if (j >= 0 && j < SEQ) {
            const uint4 kraw = *(const uint4*)(base + HID + (size_t)j * 1536 + dq);
            const uint4 vraw = *(const uint4*)(base + 2 * HID + (size_t)j * 1536 + dq);
            const __half2* kp = (const __half2*)&kraw;
            const __half2* vp = (const __half2*)&vraw;
#pragma unroll
            for (int k = 0; k < 4; k++) {
                const float2 fk = __half22float2(kp[k]);
                const float2 fv = __half22float2(vp[k]);
                kf[2 * k] = fk.x; kf[2 * k + 1] = fk.y;
                vf[2 * k] = fv.x; vf[2 * k + 1] = fv.y;
            }
        }
#pragma unroll
        for (int k = 0; k < 8; k++)
            Ks[(dq + k) * 100 + jl] = kf[k];
        float* vdst = Vs + jl * 68 + dq;
#pragma unroll
        for (int k = 0; k < 8; k++)
            vdst[k] = vf[k];
    }
    __syncthreads();

    // ---- extras pass: lane el<16 -> (query qqe = el>>1, jj = 32+(el&1)) ----
    float sx;
    {
        const int el = lane & 15;
        const int qqe = el >> 1;
        const int jje = 32 + (el & 1);
        const int ile = w * 8 + qqe;
        const int ie = q0 + ile;
        const bool ve = (dir == 0) ? (ie - 33 + jje >= 0) : (ie + jje < SEQ);
        const int jle = ile + jje;           // <= 96
        const float* qe = qs + ile * 68;
        float s = 0.f;
#pragma unroll 8
        for (int d = 0; d < 64; d++)
            s += qe[d] * Ks[d * 100 + jle];
        sx = ve ? (s * 0.125f + sbias[jje]) : -1e30f;
    }

#pragma unroll 1
    for (int qq = 0; qq < 8; qq++) {
        const int il = w * 8 + qq;
        const int i = q0 + il;
        const int jj0 = lane;                // 0..31
        const bool v0 = (dir == 0) ? (i - 33 + jj0 >= 0) : (i + jj0 < SEQ);
        const int jl0 = il + jj0;            // <= 94
        float s0 = 0.f;
        const float* qr = qs + il * 68;
#pragma unroll 4
        for (int d4 = 0; d4 < 64; d4 += 4) {
            const float4 qv = *(const float4*)(qr + d4);
            s0 += qv.x * Ks[(d4 + 0) * 100 + jl0];
            s0 += qv.y * Ks[(d4 + 1) * 100 + jl0];
            s0 += qv.z * Ks[(d4 + 2) * 100 + jl0];
            s0 += qv.w * Ks[(d4 + 3) * 100 + jl0];
        }
        s0 = v0 ? (s0 * 0.125f + sbias[jj0]) : -1e30f;

        const float se0 = __shfl_sync(0xffffffffu, sx, 2 * qq);
        const float se1 = __shfl_sync(0xffffffffu, sx, 2 * qq + 1);

        float m = fmaxf(s0, fmaxf(se0, se1));
#pragma unroll
        for (int o = 16; o > 0; o >>= 1) m = fmaxf(m, __shfl_xor_sync(0xffffffffu, m, o));
        const float e0 = __expf(s0 - m);
        const float ee0 = __expf(se0 - m);
        const float ee1 = __expf(se1 - m);
        float den = e0;
#pragma unroll
        for (int o = 16; o > 0; o >>= 1) den += __shfl_xor_sync(0xffffffffu, den, o);
        den += ee0 + ee1;

        float o0 = 0.f, o1 = 0.f;
#pragma unroll 4
        for (int jj = 0; jj < 32; jj++) {
            const float p = __shfl_sync(0xffffffffu, e0, jj);
            const float2 vv = *(const float2*)&Vs[(il + jj) * 68 + 2 * lane];
            o0 += p * vv.x;
            o1 += p * vv.y;
        }
        {
            const float2 v32 = *(const float2*)&Vs[(il + 32) * 68 + 2 * lane];
            const float2 v33 = *(const float2*)&Vs[(il + 33) * 68 + 2 * lane];
            o0 += ee0 * v32.x + ee1 * v33.x;
            o1 += ee0 * v32.y + ee1 * v33.y;
        }
        const float inv = 1.f / den;
        const size_t oi = (size_t)dir * TOK * HID + (size_t)(b * SEQ + i) * HID + h * DK + 2 * lane;
        *(uint32_t*)&g_attn_h[oi] = pack_h2(o0 * inv, o1 * inv);
    }
}

// ---------------- launch ----------------
extern "C" void kernel_launch(void* const* d_in, const int* in_sizes, int n_in,
                              void* d_out, int out_size)
{
    const float* inputs = (const float*)d_in[0];
    const float* qkv_w  = (const float*)d_in[2];
    const float* qkv_b  = (const float*)d_in[3];
    const float* rel    = (const float*)d_in[4];
    const float* hw_w   = (const float*)d_in[5];
    const float* hw_b   = (const float*)d_in[6];
    float* out = (float*)d_out;

    float *yv, *st;
    __half *qkvh, *ah, *ath, *yh, *y2h, *wq, *wh;
    cudaGetSymbolAddress((void**)&qkvh, g_qkv_h);
    cudaGetSymbolAddress((void**)&yv,   g_y);
    cudaGetSymbolAddress((void**)&st,   g_st);
    cudaGetSymbolAddress((void**)&ah,   g_act_h);
    cudaGetSymbolAddress((void**)&ath,  g_attn_h);
    cudaGetSymbolAddress((void**)&yh,   g_yh);
    cudaGetSymbolAddress((void**)&y2h,  g_y2h);
    cudaGetSymbolAddress((void**)&wq,   g_wqkv);
    cudaGetSymbolAddress((void**)&wh,   g_whw);

    cudaFuncSetAttribute(gemm_fused, cudaFuncAttributeMaxDynamicSharedMemorySize, GSMEM);
    cudaFuncSetAttribute(attn_v6, cudaFuncAttributeMaxDynamicSharedMemorySize, ATT_SMEM);

    prep_all<<<10240, 256>>>(qkv_w, hw_w, inputs, wq, wh);

    for (int l = 0; l < 2; l++) {
        const size_t QL = (size_t)l * 2 * 4 * HID * HID;
        const size_t HL = (size_t)l * 2 * 2 * 2 * HID * HID;
        const float* qb = qkv_b + (size_t)l * 2 * 4 * HID;
        const float* hb = hw_b + (size_t)l * 2 * 2 * 2 * HID;

        // QKV: fp16 output only (mode 0, C=null)
        gemm_fused<<<NCTA, 256, GSMEM>>>(
            ah, wq + QL, qb, nullptr, qkvh,
            nullptr, nullptr, nullptr,
            3 * HID, (size_t)4 * HID * HID, (size_t)4 * HID, (size_t)TOK * 3 * HID, 0, 0, 768);

        attn_v6<<<dim3(SEQ / 64, BATCH * NHEAD, 2), 256, ATT_SMEM>>>(
            rel + (size_t)l * 2 * NHEAD * WIN);

        // out projection: y fp32 + fp16 (mode 1)
        gemm_fused<<<NCTA, 256, GSMEM>>>(
            ath, wq + QL + (size_t)3 * HID * HID,
            qb + 3 * HID, yv, yh, nullptr, nullptr, nullptr,
            HID, (size_t)4 * HID * HID, (size_t)4 * HID, (size_t)TOK * HID, 1, 0, 256);

        // highway 1 (mode 2)
        gemm_fused<<<NCTA, 256, GSMEM>>>(
            yh, wh + HL, hb, nullptr, y2h,
            yv, nullptr, nullptr,
            2 * HID, (size_t)2 * 2 * HID * HID, (size_t)2 * 2 * HID, 0, 2, 0, 512);

        // highway 2 (mode 3)
        gemm_fused<<<NCTA, 256, GSMEM>>>(
            y2h, wh + HL + (size_t)2 * HID * HID,
            hb + 2 * HID, nullptr, ah,
            yv, st, out + (size_t)l * TOK * 2 * HID,
            2 * HID, (size_t)2 * 2 * HID * HID, (size_t)2 * 2 * HID, 0, 3, l > 0 ? 1 : 0, 512);
    }
}

// round 13
// speedup vs baseline: 1.1150x; 1.1150x over previous
#include <cuda_runtime.h>
#include <cuda_fp16.h>
#include <cstdint>
#include <cstddef>

#define NHEAD 8
#define HID 512
#define DK 64
#define SEQ 1024
#define BATCH 4
#define TOK 4096
#define WIN 34
#define KDIM 512

#define BK 64
#define OFF_B 16384
#define STAGE_B 32768                  // A | B
#define GSMEM (3 * STAGE_B)            // 98304, 3-stage pipeline
#define NCTA 296

// ---------------- scratch ----------------
__device__ float g_st  [2ull * TOK * HID];
__device__ float g_qkv [2ull * TOK * 3 * HID];
__device__ float g_y   [2ull * TOK * HID];
__device__ __half g_act_h [2ull * TOK * HID];
__device__ __half g_attn_h[2ull * TOK * HID];
__device__ __half g_yh    [2ull * TOK * HID];
__device__ __half g_y2h   [2ull * TOK * HID];
__device__ __half g_wqkv  [4194304];
__device__ __half g_whw   [4194304];

// ---------------- helpers ----------------
__device__ __forceinline__ uint32_t s2u(const void* p) {
    uint32_t a;
    asm("{ .reg .u64 t; cvta.to.shared.u64 t, %1; cvt.u32.u64 %0, t; }" : "=r"(a) : "l"(p));
    return a;
}
__device__ __forceinline__ void cpasync16(uint32_t dst, const void* src) {
    asm volatile("cp.async.cg.shared.global [%0], [%1], 16;" :: "r"(dst), "l"(src));
}
__device__ __forceinline__ void ldmx4(uint32_t* d, uint32_t a) {
    asm volatile("ldmatrix.sync.aligned.m8n8.x4.shared.b16 {%0,%1,%2,%3}, [%4];"
        : "=r"(d[0]), "=r"(d[1]), "=r"(d[2]), "=r"(d[3]) : "r"(a));
}
__device__ __forceinline__ void mma16816(float* c, const uint32_t* a, const uint32_t* b) {
    asm volatile("mma.sync.aligned.m16n8k16.row.col.f32.f16.f16.f32 "
        "{%0,%1,%2,%3}, {%4,%5,%6,%7}, {%8,%9}, {%0,%1,%2,%3};"
        : "+f"(c[0]), "+f"(c[1]), "+f"(c[2]), "+f"(c[3])
        : "r"(a[0]), "r"(a[1]), "r"(a[2]), "r"(a[3]), "r"(b[0]), "r"(b[1]));
}
__device__ __forceinline__ uint32_t pack_h2(float x, float y) {
    __half2 t = __floats2half2_rn(x, y);
    return *(uint32_t*)&t;
}

// ---------------- prep (merged): weight conversion + activation init ----------
__global__ void prep_all(const float* __restrict__ qkvw, const float* __restrict__ hww,
                         const float* __restrict__ in,
                         __half* __restrict__ dq, __half* __restrict__ dh)
{
    const size_t bi = blockIdx.x;
    if (bi < 4096) {
        const size_t i = bi * blockDim.x + threadIdx.x;
        float4 v = ((const float4*)qkvw)[i];
        *(uint2*)(dq + 4 * i) = make_uint2(pack_h2(v.x, v.y), pack_h2(v.z, v.w));
    } else if (bi < 8192) {
        const size_t idx = (bi - 4096) * blockDim.x + threadIdx.x;
        const size_t m   = idx >> 17;
        const size_t rem = idx & 131071;
        const int    r   = (int)(rem >> 7);
        const size_t c4  = rem & 127;
        const int dr = (r < 512) ? (2 * r) : (2 * (r - 512) + 1);
        float4 v = ((const float4*)hww)[idx];
        const size_t d = (m << 17) + (size_t)dr * 128 + c4;
        *(uint2*)(dh + 4 * d) = make_uint2(pack_h2(v.x, v.y), pack_h2(v.z, v.w));
    } else {
        const size_t idx = (bi - 8192) * blockDim.x + threadIdx.x;
        const float4 v = *(const float4*)(in + idx * 4);
        const uint2 p = make_uint2(pack_h2(v.x, v.y), pack_h2(v.z, v.w));
        *(uint2*)&g_act_h[idx * 4] = p;
        *(uint2*)&g_act_h[(size_t)TOK * HID + idx * 4] = p;
    }
}

// ---------------- persistent fused HMMA GEMM (R11 version, verbatim) --------
__global__ __launch_bounds__(256, 2)
void gemm_fused(const __half* __restrict__ A, const __half* __restrict__ B,
                const float* __restrict__ bias, float* __restrict__ C,
                __half* __restrict__ Sh,
                float* __restrict__ Yv, float* __restrict__ St, float* __restrict__ Out,
                int N, size_t sB, size_t sbias, size_t sC, int mode, int add_res,
                int ntiles)
{
    extern __shared__ char smem[];
    const uint32_t sbase = s2u(smem);
    const int tid = threadIdx.x, lane = tid & 31, wid = tid >> 5;
    const int wm = wid & 1, wn = wid >> 1;

    const int bx = (int)blockIdx.x;
    const int nt = (bx < ntiles) ? ((ntiles - 1 - bx) / (int)gridDim.x + 1) : 0;
    if (nt == 0) return;
    const int total = nt * 8;

    const int r  = tid >> 1;
    const int c0 = (tid & 1) * 4;
    const uint32_t r7 = (uint32_t)(r & 7);
    uint32_t swz[4];
#pragma unroll
    for (int u = 0; u < 4; u++)
        swz[u] = (uint32_t)r * 128 + ((((uint32_t)(c0 + u)) ^ r7) << 4);

    const int m8 = lane >> 3, l7 = lane & 7;
    const uint32_t a_row = (uint32_t)(wm * 64 + (m8 & 1) * 8 + l7) * 128;
    const uint32_t b_row = (uint32_t)(wn * 32 + (m8 >> 1) * 8 + l7) * 128;
    uint32_t acol[4], bcol[4];
#pragma unroll
    for (int kk = 0; kk < 4; kk++) {
        acol[kk] = ((uint32_t)(kk * 2 + (m8 >> 1)) ^ (uint32_t)l7) << 4;
        bcol[kk] = ((uint32_t)(kk * 2 + (m8 & 1)) ^ (uint32_t)l7) << 4;
    }

    float acc[4][4][4];
#pragma unroll
    for (int i = 0; i < 4; i++)
#pragma unroll
        for (int j = 0; j < 4; j++)
#pragma unroll
            for (int k = 0; k < 4; k++) acc[i][j][k] = 0.f;

#define LOAD_G(g) do {                                                             \
        const int _t = bx + ((g) >> 3) * (int)gridDim.x;                           \
        const int _dir = _t & 1, _u = _t >> 1;                                     \
        const int _bm = (_u & 31) * 128, _bn = (_u >> 5) * 128;                    \
        const int _ke = ((g) & 7) * BK + c0 * 8;                                   \
        const __half* _Ap = A + (size_t)_dir * (TOK * KDIM)                        \
                              + (size_t)(_bm + r) * KDIM + _ke;                    \
        const __half* _Bp = B + (size_t)_dir * sB + (size_t)(_bn + r) * KDIM + _ke;\
        const uint32_t _sb = sbase + (uint32_t)((g) % 3) * STAGE_B;                \
        cpasync16(_sb + swz[0],         _Ap);                                      \
        cpasync16(_sb + swz[1],         _Ap + 8);                                  \
        cpasync16(_sb + swz[2],         _Ap + 16);                                 \
        cpasync16(_sb + swz[3],         _Ap + 24);                                 \
        cpasync16(_sb + OFF_B + swz[0], _Bp);                                      \
        cpasync16(_sb + OFF_B + swz[1], _Bp + 8);                                  \
        cpasync16(_sb + OFF_B + swz[2], _Bp + 16);                                 \
        cpasync16(_sb + OFF_B + swz[3], _Bp + 24);                                 \
        asm volatile("cp.async.commit_group;" ::: "memory");                       \
    } while (0)

    LOAD_G(0);
    LOAD_G(1);

    const int gr = lane >> 2, gc = (lane & 3) * 2;

#pragma unroll 1
    for (int g = 0; g < total; g++) {
        if (g < total - 1) asm volatile("cp.async.wait_group 1;" ::: "memory");
        else               asm volatile("cp.async.wait_group 0;" ::: "memory");
        __syncthreads();
        if (g + 2 < total) LOAD_G(g + 2);

        const uint32_t sb = sbase + (uint32_t)(g % 3) * STAGE_B;
#pragma unroll
        for (int kk = 0; kk < 4; kk++) {
            uint32_t a[4][4], b[2][4];
#pragma unroll
            for (int nj = 0; nj < 2; nj++)
                ldmx4(b[nj], sb + OFF_B + b_row + nj * 2048 + bcol[kk]);
#pragma unroll
            for (int mi = 0; mi < 4; mi++)
                ldmx4(a[mi], sb + a_row + mi * 2048 + acol[kk]);
#pragma unroll
            for (int mi = 0; mi < 4; mi++)
#pragma unroll
                for (int ni = 0; ni < 4; ni++)
                    mma16816(acc[mi][ni], a[mi], &b[ni >> 1][(ni & 1) * 2]);
        }

        if ((g & 7) == 7) {
            const int t = bx + (g >> 3) * (int)gridDim.x;
            const int dir = t & 1, u = t >> 1;
            const int bm = (u & 31) * 128, bn = (u >> 5) * 128;
            const float* bs = bias + (size_t)dir * sbias;

            if (mode <= 1) {
                float* Cp = C + (size_t)dir * sC;
                __half* SH = Sh ? (Sh + (size_t)dir * sC) : nullptr;
#pragma unroll
                for (int mi = 0; mi < 4; mi++) {
#pragma unroll
                    for (int ni = 0; ni < 4; ni++) {
                        const int row0 = bm + wm * 64 + mi * 16 + gr;
                        const int col  = bn + wn * 32 + ni * 8 + gc;
                        const float b0 = bs[col], b1 = bs[col + 1];
                        const float v00 = acc[mi][ni][0] + b0, v01 = acc[mi][ni][1] + b1;
                        const float v10 = acc[mi][ni][2] + b0, v11 = acc[mi][ni][3] + b1;
                        *(float2*)&Cp[(size_t)row0 * N + col]       = make_float2(v00, v01);
                        *(float2*)&Cp[(size_t)(row0 + 8) * N + col] = make_float2(v10, v11);
                        if (mode == 1) {
                            *(uint32_t*)&SH[(size_t)row0 * N + col]       = pack_h2(v00, v01);
                            *(uint32_t*)&SH[(size_t)(row0 + 8) * N + col] = pack_h2(v10, v11);
                        }
                    }
                }
            } else {
                float* Y = Yv + (size_t)dir * TOK * HID;
                float* S = St ? (St + (size_t)dir * TOK * HID) : nullptr;
                __half* SH = Sh + (size_t)dir * TOK * HID;
#pragma unroll
                for (int mi = 0; mi < 4; mi++) {
#pragma unroll
                    for (int ni = 0; ni < 4; ni++) {
                        const int row0 = bm + wm * 64 + mi * 16 + gr;
                        const int col  = bn + wn * 32 + ni * 8 + gc;
                        const int j    = col >> 1;
                        const float bnl = bs[j], bgt = bs[j + HID];
#pragma unroll
                        for (int rr = 0; rr < 2; rr++) {
                            const int row = row0 + rr * 8;
                            const float n = acc[mi][ni][rr * 2]     + bnl;
                            const float gg = acc[mi][ni][rr * 2 + 1] + bgt;
                            const size_t o = (size_t)row * HID + j;
                            const float yo = Y[o];
                            const float s = 1.f / (1.f + __expf(-gg));
                            float v = s * yo + (1.f - s) * fmaxf(n, 0.f);
                            if (mode == 2) {
                                Y[o] = v;
                            } else {
                                if (add_res) v += S[o];
                                S[o] = v;
                                Out[(size_t)row * (2 * HID) + (size_t)dir * HID + j] = v;
                            }
                            SH[o] = __float2half(v);
                        }
                    }
                }
            }
#pragma unroll
            for (int i = 0; i < 4; i++)
#pragma unroll
                for (int j = 0; j < 4; j++)
#pragma unroll
                    for (int k = 0; k < 4; k++) acc[i][j][k] = 0.f;
        }
    }
#undef LOAD_G
}

// ---------------- banded local attention v7 ---------------------------------
// v5 structure (fp32 qkv input, fp32 K/q smem, shuffle-broadcast probs) with
// ONE change: V stored in smem as __half2 (converted once at tile load) ->
// V-loop LDS halves from 64-bit to 32-bit (1 crossbar cycle/jj instead of 2).
// smem floats: Ks[64][100]=6400, qs[64][68]=4352, sbias 34, pad 2,
//              Vsh = 97*68 halves = 3298 float-equiv.  total 14088 floats.
#define ATT_SMEM (14088 * 4)
__global__ void attn_v7(const float* __restrict__ rel_l)
{
    extern __shared__ float sm[];
    float* Ks = sm;                         // [64][100] transposed K: d-major
    float* qs = sm + 6400;                  // [64][68]
    float* sbias = sm + 10752;              // [34]
    __half* Vsh = (__half*)(sm + 10788);    // [97][68] halves

    const int dir = blockIdx.z;
    const int bh = blockIdx.y;
    const int b = bh >> 3, h = bh & 7;
    const int q0 = blockIdx.x * 64;
    const int tid = threadIdx.x, w = tid >> 5, lane = tid & 31;
    const int W0 = (dir == 0) ? (q0 - 33) : q0;

    const float* base = g_qkv + (size_t)dir * TOK * (3 * HID)
                              + (size_t)(b * SEQ) * (3 * HID) + h * DK;

    if (tid < WIN)
        sbias[tid] = rel_l[((size_t)dir * NHEAD + h) * WIN + tid];

    // load q tile
    for (int idx = tid; idx < 64 * 16; idx += 256) {
        const int row = idx >> 4, dq = (idx & 15) * 4;
        const float4 v = *(const float4*)(base + (size_t)(q0 + row) * 1536 + dq);
        float* qp = qs + row * 68 + dq;
        qp[0] = v.x; qp[1] = v.y; qp[2] = v.z; qp[3] = v.w;
    }
    // load K (transposed, fp32) and V window (converted to half2)
    for (int idx = tid; idx < 97 * 16; idx += 256) {
        const int jl = idx >> 4, dq = (idx & 15) * 4;
        const int j = W0 + jl;
        float4 kv = make_float4(0.f, 0.f, 0.f, 0.f);
        float4 vv = make_float4(0.f, 0.f, 0.f, 0.f);
        if (j >= 0 && j < SEQ) {
            kv = *(const float4*)(base + HID + (size_t)j * 1536 + dq);
            vv = *(const float4*)(base + 2 * HID + (size_t)j * 1536 + dq);
        }
        Ks[(dq + 0) * 100 + jl] = kv.x;
        Ks[(dq + 1) * 100 + jl] = kv.y;
        Ks[(dq + 2) * 100 + jl] = kv.z;
        Ks[(dq + 3) * 100 + jl] = kv.w;
        *(uint32_t*)&Vsh[jl * 68 + dq]     = pack_h2(vv.x, vv.y);
        *(uint32_t*)&Vsh[jl * 68 + dq + 2] = pack_h2(vv.z, vv.w);
    }
    __syncthreads();

    // ---- extras pass: lane el<16 -> (query qqe = el>>1, jj = 32+(el&1)) ----
    float sx;
    {
        const int el = lane & 15;
        const int qqe = el >> 1;
        const int jje = 32 + (el & 1);
        const int ile = w * 8 + qqe;
        const int ie = q0 + ile;
        const bool ve = (dir == 0) ? (ie - 33 + jje >= 0) : (ie + jje < SEQ);
        const int jle = ile + jje;           // <= 96
        const float* qe = qs + ile * 68;
        float s = 0.f;
#pragma unroll 8
        for (int d = 0; d < 64; d++)
            s += qe[d] * Ks[d * 100 + jle];
        sx = ve ? (s * 0.125f + sbias[jje]) : -1e30f;
    }

#pragma unroll 1
    for (int qq = 0; qq < 8; qq++) {
        const int il = w * 8 + qq;
        const int i = q0 + il;
        const int jj0 = lane;                // 0..31
        const bool v0 = (dir == 0) ? (i - 33 + jj0 >= 0) : (i + jj0 < SEQ);
        const int jl0 = il + jj0;            // <= 94
        float s0 = 0.f;
        const float* qr = qs + il * 68;
#pragma unroll 4
        for (int d4 = 0; d4 < 64; d4 += 4) {
            const float4 qv = *(const float4*)(qr + d4);
            s0 += qv.x * Ks[(d4 + 0) * 100 + jl0];
            s0 += qv.y * Ks[(d4 + 1) * 100 + jl0];
            s0 += qv.z * Ks[(d4 + 2) * 100 + jl0];
            s0 += qv.w * Ks[(d4 + 3) * 100 + jl0];
        }
        s0 = v0 ? (s0 * 0.125f + sbias[jj0]) : -1e30f;

        const float se0 = __shfl_sync(0xffffffffu, sx, 2 * qq);
        const float se1 = __shfl_sync(0xffffffffu, sx, 2 * qq + 1);

        float m = fmaxf(s0, fmaxf(se0, se1));
#pragma unroll
        for (int o = 16; o > 0; o >>= 1) m = fmaxf(m, __shfl_xor_sync(0xffffffffu, m, o));
        const float e0 = __expf(s0 - m);
        const float ee0 = __expf(se0 - m);
        const float ee1 = __expf(se1 - m);
        float den = e0;
#pragma unroll
        for (int o = 16; o > 0; o >>= 1) den += __shfl_xor_sync(0xffffffffu, den, o);
        den += ee0 + ee1;

        // V accumulation: half2 LDS (1 crossbar cycle/jj)
        float o0 = 0.f, o1 = 0.f;
#pragma unroll 4
        for (int jj = 0; jj < 32; jj++) {
            const float p = __shfl_sync(0xffffffffu, e0, jj);
            const float2 vv = __half22float2(*(const __half2*)&Vsh[(il + jj) * 68 + 2 * lane]);
            o0 += p * vv.x;
            o1 += p * vv.y;
        }
        {
            const float2 v32 = __half22float2(*(const __half2*)&Vsh[(il + 32) * 68 + 2 * lane]);
            const float2 v33 = __half22float2(*(const __half2*)&Vsh[(il + 33) * 68 + 2 * lane]);
            o0 += ee0 * v32.x + ee1 * v33.x;
            o1 += ee0 * v32.y + ee1 * v33.y;
        }
        const float inv = 1.f / den;
        const size_t oi = (size_t)dir * TOK * HID + (size_t)(b * SEQ + i) * HID + h * DK + 2 * lane;
        *(uint32_t*)&g_attn_h[oi] = pack_h2(o0 * inv, o1 * inv);
    }
}

// ---------------- launch ----------------
extern "C" void kernel_launch(void* const* d_in, const int* in_sizes, int n_in,
                              void* d_out, int out_size)
{
    const float* inputs = (const float*)d_in[0];
    const float* qkv_w  = (const float*)d_in[2];
    const float* qkv_b  = (const float*)d_in[3];
    const float* rel    = (const float*)d_in[4];
    const float* hw_w   = (const float*)d_in[5];
    const float* hw_b   = (const float*)d_in[6];
    float* out = (float*)d_out;

    float *qkvp, *yv, *st;
    __half *ah, *ath, *yh, *y2h, *wq, *wh;
    cudaGetSymbolAddress((void**)&qkvp, g_qkv);
    cudaGetSymbolAddress((void**)&yv,   g_y);
    cudaGetSymbolAddress((void**)&st,   g_st);
    cudaGetSymbolAddress((void**)&ah,   g_act_h);
    cudaGetSymbolAddress((void**)&ath,  g_attn_h);
    cudaGetSymbolAddress((void**)&yh,   g_yh);
    cudaGetSymbolAddress((void**)&y2h,  g_y2h);
    cudaGetSymbolAddress((void**)&wq,   g_wqkv);
    cudaGetSymbolAddress((void**)&wh,   g_whw);

    cudaFuncSetAttribute(gemm_fused, cudaFuncAttributeMaxDynamicSharedMemorySize, GSMEM);
    cudaFuncSetAttribute(attn_v7, cudaFuncAttributeMaxDynamicSharedMemorySize, ATT_SMEM);

    prep_all<<<10240, 256>>>(qkv_w, hw_w, inputs, wq, wh);

    for (int l = 0; l < 2; l++) {
        const size_t QL = (size_t)l * 2 * 4 * HID * HID;
        const size_t HL = (size_t)l * 2 * 2 * 2 * HID * HID;
        const float* qb = qkv_b + (size_t)l * 2 * 4 * HID;
        const float* hb = hw_b + (size_t)l * 2 * 2 * 2 * HID;

        // QKV: fp32 out (mode 0)
        gemm_fused<<<NCTA, 256, GSMEM>>>(
            ah, wq + QL, qb, qkvp, nullptr,
            nullptr, nullptr, nullptr,
            3 * HID, (size_t)4 * HID * HID, (size_t)4 * HID, (size_t)TOK * 3 * HID, 0, 0, 768);

        attn_v7<<<dim3(SEQ / 64, BATCH * NHEAD, 2), 256, ATT_SMEM>>>(
            rel + (size_t)l * 2 * NHEAD * WIN);

        // out projection: y fp32 + fp16 (mode 1)
        gemm_fused<<<NCTA, 256, GSMEM>>>(
            ath, wq + QL + (size_t)3 * HID * HID,
            qb + 3 * HID, yv, yh, nullptr, nullptr, nullptr,
            HID, (size_t)4 * HID * HID, (size_t)4 * HID, (size_t)TOK * HID, 1, 0, 256);

        // highway 1 (mode 2)
        gemm_fused<<<NCTA, 256, GSMEM>>>(
            yh, wh + HL, hb, nullptr, y2h,
            yv, nullptr, nullptr,
            2 * HID, (size_t)2 * 2 * HID * HID, (size_t)2 * 2 * HID, 0, 2, 0, 512);

        // highway 2 (mode 3)
        gemm_fused<<<NCTA, 256, GSMEM>>>(
            y2h, wh + HL + (size_t)2 * HID * HID,
            hb + 2 * HID, nullptr, ah,
            yv, st, out + (size_t)l * TOK * 2 * HID,
            2 * HID, (size_t)2 * 2 * HID * HID, (size_t)2 * 2 * HID, 0, 3, l > 0 ? 1 : 0, 512);
    }
}

// round 14
// speedup vs baseline: 1.1544x; 1.0353x over previous
#include <cuda_runtime.h>
#include <cuda_fp16.h>
#include <cstdint>
#include <cstddef>

#define NHEAD 8
#define HID 512
#define DK 64
#define SEQ 1024
#define BATCH 4
#define TOK 4096
#define WIN 34
#define KDIM 512

#define BK 64
#define OFF_B 16384
#define STAGE_B 32768                  // A | B
#define GSMEM (3 * STAGE_B)            // 98304, 3-stage pipeline
#define NCTA 296

// ---------------- scratch ----------------
__device__ float g_st  [2ull * TOK * HID];
__device__ float g_qkv [2ull * TOK * 3 * HID];
__device__ __half g_act_h [2ull * TOK * HID];
__device__ __half g_attn_h[2ull * TOK * HID];
__device__ __half g_yh    [2ull * TOK * HID];
__device__ __half g_y2h   [2ull * TOK * HID];
__device__ __half g_wqkv  [4194304];
__device__ __half g_whw   [4194304];

// ---------------- helpers ----------------
__device__ __forceinline__ uint32_t s2u(const void* p) {
    uint32_t a;
    asm("{ .reg .u64 t; cvta.to.shared.u64 t, %1; cvt.u32.u64 %0, t; }" : "=r"(a) : "l"(p));
    return a;
}
__device__ __forceinline__ void cpasync16(uint32_t dst, const void* src) {
    asm volatile("cp.async.cg.shared.global [%0], [%1], 16;" :: "r"(dst), "l"(src));
}
__device__ __forceinline__ void ldmx4(uint32_t* d, uint32_t a) {
    asm volatile("ldmatrix.sync.aligned.m8n8.x4.shared.b16 {%0,%1,%2,%3}, [%4];"
        : "=r"(d[0]), "=r"(d[1]), "=r"(d[2]), "=r"(d[3]) : "r"(a));
}
__device__ __forceinline__ void mma16816(float* c, const uint32_t* a, const uint32_t* b) {
    asm volatile("mma.sync.aligned.m16n8k16.row.col.f32.f16.f16.f32 "
        "{%0,%1,%2,%3}, {%4,%5,%6,%7}, {%8,%9}, {%0,%1,%2,%3};"
        : "+f"(c[0]), "+f"(c[1]), "+f"(c[2]), "+f"(c[3])
        : "r"(a[0]), "r"(a[1]), "r"(a[2]), "r"(a[3]), "r"(b[0]), "r"(b[1]));
}
__device__ __forceinline__ uint32_t pack_h2(float x, float y) {
    __half2 t = __floats2half2_rn(x, y);
    return *(uint32_t*)&t;
}

// ---------------- prep (merged): weight conversion + activation init ----------
__global__ void prep_all(const float* __restrict__ qkvw, const float* __restrict__ hww,
                         const float* __restrict__ in,
                         __half* __restrict__ dq, __half* __restrict__ dh)
{
    const size_t bi = blockIdx.x;
    if (bi < 4096) {
        const size_t i = bi * blockDim.x + threadIdx.x;
        float4 v = ((const float4*)qkvw)[i];
        *(uint2*)(dq + 4 * i) = make_uint2(pack_h2(v.x, v.y), pack_h2(v.z, v.w));
    } else if (bi < 8192) {
        const size_t idx = (bi - 4096) * blockDim.x + threadIdx.x;
        const size_t m   = idx >> 17;
        const size_t rem = idx & 131071;
        const int    r   = (int)(rem >> 7);
        const size_t c4  = rem & 127;
        const int dr = (r < 512) ? (2 * r) : (2 * (r - 512) + 1);
        float4 v = ((const float4*)hww)[idx];
        const size_t d = (m << 17) + (size_t)dr * 128 + c4;
        *(uint2*)(dh + 4 * d) = make_uint2(pack_h2(v.x, v.y), pack_h2(v.z, v.w));
    } else {
        const size_t idx = (bi - 8192) * blockDim.x + threadIdx.x;
        const float4 v = *(const float4*)(in + idx * 4);
        const uint2 p = make_uint2(pack_h2(v.x, v.y), pack_h2(v.z, v.w));
        *(uint2*)&g_act_h[idx * 4] = p;
        *(uint2*)&g_act_h[(size_t)TOK * HID + idx * 4] = p;
    }
}

// ---------------- persistent fused HMMA GEMM -------------------------------
// mode<=1: fp32 C (if C != null) and/or fp16 Sh (if Sh != null)
// mode 2: highway mid:  v = sig(g)*half2float(Gh) + (1-sig)*relu(n); Sh = h(v)
// mode 3: highway final: v = gate(Gh) (+St); St=v; Out=v; Sh=h(v)
__global__ __launch_bounds__(256, 2)
void gemm_fused(const __half* __restrict__ A, const __half* __restrict__ B,
                const float* __restrict__ bias, float* __restrict__ C,
                __half* __restrict__ Sh, const __half* __restrict__ Gh,
                float* __restrict__ St, float* __restrict__ Out,
                int N, size_t sB, size_t sbias, size_t sC, int mode, int add_res,
                int ntiles)
{
    extern __shared__ char smem[];
    const uint32_t sbase = s2u(smem);
    const int tid = threadIdx.x, lane = tid & 31, wid = tid >> 5;
    const int wm = wid & 1, wn = wid >> 1;

    const int bx = (int)blockIdx.x;
    const int nt = (bx < ntiles) ? ((ntiles - 1 - bx) / (int)gridDim.x + 1) : 0;
    if (nt == 0) return;
    const int total = nt * 8;

    const int r  = tid >> 1;
    const int c0 = (tid & 1) * 4;
    const uint32_t r7 = (uint32_t)(r & 7);
    uint32_t swz[4];
#pragma unroll
    for (int u = 0; u < 4; u++)
        swz[u] = (uint32_t)r * 128 + ((((uint32_t)(c0 + u)) ^ r7) << 4);

    const int m8 = lane >> 3, l7 = lane & 7;
    const uint32_t a_row = (uint32_t)(wm * 64 + (m8 & 1) * 8 + l7) * 128;
    const uint32_t b_row = (uint32_t)(wn * 32 + (m8 >> 1) * 8 + l7) * 128;
    uint32_t acol[4], bcol[4];
#pragma unroll
    for (int kk = 0; kk < 4; kk++) {
        acol[kk] = ((uint32_t)(kk * 2 + (m8 >> 1)) ^ (uint32_t)l7) << 4;
        bcol[kk] = ((uint32_t)(kk * 2 + (m8 & 1)) ^ (uint32_t)l7) << 4;
    }

    float acc[4][4][4];
#pragma unroll
    for (int i = 0; i < 4; i++)
#pragma unroll
        for (int j = 0; j < 4; j++)
#pragma unroll
            for (int k = 0; k < 4; k++) acc[i][j][k] = 0.f;

#define LOAD_G(g) do {                                                             \
        const int _t = bx + ((g) >> 3) * (int)gridDim.x;                           \
        const int _dir = _t & 1, _u = _t >> 1;                                     \
        const int _bm = (_u & 31) * 128, _bn = (_u >> 5) * 128;                    \
        const int _ke = ((g) & 7) * BK + c0 * 8;                                   \
        const __half* _Ap = A + (size_t)_dir * (TOK * KDIM)                        \
                              + (size_t)(_bm + r) * KDIM + _ke;                    \
        const __half* _Bp = B + (size_t)_dir * sB + (size_t)(_bn + r) * KDIM + _ke;\
        const uint32_t _sb = sbase + (uint32_t)((g) % 3) * STAGE_B;                \
        cpasync16(_sb + swz[0],         _Ap);                                      \
        cpasync16(_sb + swz[1],         _Ap + 8);                                  \
        cpasync16(_sb + swz[2],         _Ap + 16);                                 \
        cpasync16(_sb + swz[3],         _Ap + 24);                                 \
        cpasync16(_sb + OFF_B + swz[0], _Bp);                                      \
        cpasync16(_sb + OFF_B + swz[1], _Bp + 8);                                  \
        cpasync16(_sb + OFF_B + swz[2], _Bp + 16);                                 \
        cpasync16(_sb + OFF_B + swz[3], _Bp + 24);                                 \
        asm volatile("cp.async.commit_group;" ::: "memory");                       \
    } while (0)

    LOAD_G(0);
    LOAD_G(1);

    const int gr = lane >> 2, gc = (lane & 3) * 2;

#pragma unroll 1
    for (int g = 0; g < total; g++) {
        if (g < total - 1) asm volatile("cp.async.wait_group 1;" ::: "memory");
        else               asm volatile("cp.async.wait_group 0;" ::: "memory");
        __syncthreads();
        if (g + 2 < total) LOAD_G(g + 2);

        const uint32_t sb = sbase + (uint32_t)(g % 3) * STAGE_B;
#pragma unroll
        for (int kk = 0; kk < 4; kk++) {
            uint32_t a[4][4], b[2][4];
#pragma unroll
            for (int nj = 0; nj < 2; nj++)
                ldmx4(b[nj], sb + OFF_B + b_row + nj * 2048 + bcol[kk]);
#pragma unroll
            for (int mi = 0; mi < 4; mi++)
                ldmx4(a[mi], sb + a_row + mi * 2048 + acol[kk]);
#pragma unroll
            for (int mi = 0; mi < 4; mi++)
#pragma unroll
                for (int ni = 0; ni < 4; ni++)
                    mma16816(acc[mi][ni], a[mi], &b[ni >> 1][(ni & 1) * 2]);
        }

        if ((g & 7) == 7) {
            const int t = bx + (g >> 3) * (int)gridDim.x;
            const int dir = t & 1, u = t >> 1;
            const int bm = (u & 31) * 128, bn = (u >> 5) * 128;
            const float* bs = bias + (size_t)dir * sbias;

            if (mode <= 1) {
                float* Cp = C ? (C + (size_t)dir * sC) : nullptr;
                __half* SH = Sh ? (Sh + (size_t)dir * sC) : nullptr;
#pragma unroll
                for (int mi = 0; mi < 4; mi++) {
#pragma unroll
                    for (int ni = 0; ni < 4; ni++) {
                        const int row0 = bm + wm * 64 + mi * 16 + gr;
                        const int col  = bn + wn * 32 + ni * 8 + gc;
                        const float b0 = bs[col], b1 = bs[col + 1];
                        const float v00 = acc[mi][ni][0] + b0, v01 = acc[mi][ni][1] + b1;
                        const float v10 = acc[mi][ni][2] + b0, v11 = acc[mi][ni][3] + b1;
                        if (Cp) {
                            *(float2*)&Cp[(size_t)row0 * N + col]       = make_float2(v00, v01);
                            *(float2*)&Cp[(size_t)(row0 + 8) * N + col] = make_float2(v10, v11);
                        }
                        if (SH) {
                            *(uint32_t*)&SH[(size_t)row0 * N + col]       = pack_h2(v00, v01);
                            *(uint32_t*)&SH[(size_t)(row0 + 8) * N + col] = pack_h2(v10, v11);
                        }
                    }
                }
            } else {
                const __half* G = Gh + (size_t)dir * TOK * HID;
                float* S = St ? (St + (size_t)dir * TOK * HID) : nullptr;
                __half* SH = Sh + (size_t)dir * TOK * HID;
#pragma unroll
                for (int mi = 0; mi < 4; mi++) {
#pragma unroll
                    for (int ni = 0; ni < 4; ni++) {
                        const int row0 = bm + wm * 64 + mi * 16 + gr;
                        const int col  = bn + wn * 32 + ni * 8 + gc;
                        const int j    = col >> 1;
                        const float bnl = bs[j], bgt = bs[j + HID];
#pragma unroll
                        for (int rr = 0; rr < 2; rr++) {
                            const int row = row0 + rr * 8;
                            const float n = acc[mi][ni][rr * 2]     + bnl;
                            const float gg = acc[mi][ni][rr * 2 + 1] + bgt;
                            const size_t o = (size_t)row * HID + j;
                            const float yo = __half2float(G[o]);
                            const float s = 1.f / (1.f + __expf(-gg));
                            float v = s * yo + (1.f - s) * fmaxf(n, 0.f);
                            if (mode == 3) {
                                if (add_res) v += S[o];
                                S[o] = v;
                                Out[(size_t)row * (2 * HID) + (size_t)dir * HID + j] = v;
                            }
                            SH[o] = __float2half(v);
                        }
                    }
                }
            }
#pragma unroll
            for (int i = 0; i < 4; i++)
#pragma unroll
                for (int j = 0; j < 4; j++)
#pragma unroll
                    for (int k = 0; k < 4; k++) acc[i][j][k] = 0.f;
        }
    }
#undef LOAD_G
}

// ---------------- banded local attention v8 ---------------------------------
// v7 + K stored in smem as half2 pairs (d-major, row stride 101 words for
// conflict-free stores). Score-loop LDS words halve; fp32 accumulation.
// smem words: Ksh 32*101=3232, qs 64*68=4352, sbias 34 + pad 2,
//             Vsh 97*68 halves = 3298 words. total 10918 words.
#define ATT_SMEM (10920 * 4)
__global__ void attn_v8(const float* __restrict__ rel_l)
{
    extern __shared__ float sm[];
    __half2* Ksh = (__half2*)sm;            // [32][101] (d-pair major)
    float* qs = sm + 3232;                  // [64][68]
    float* sbias = sm + 7584;               // [34]
    __half* Vsh = (__half*)(sm + 7620);     // [97][68] halves

    const int dir = blockIdx.z;
    const int bh = blockIdx.y;
    const int b = bh >> 3, h = bh & 7;
    const int q0 = blockIdx.x * 64;
    const int tid = threadIdx.x, w = tid >> 5, lane = tid & 31;
    const int W0 = (dir == 0) ? (q0 - 33) : q0;

    const float* base = g_qkv + (size_t)dir * TOK * (3 * HID)
                              + (size_t)(b * SEQ) * (3 * HID) + h * DK;

    if (tid < WIN)
        sbias[tid] = rel_l[((size_t)dir * NHEAD + h) * WIN + tid];

    // load q tile (fp32)
    for (int idx = tid; idx < 64 * 16; idx += 256) {
        const int row = idx >> 4, dq = (idx & 15) * 4;
        const float4 v = *(const float4*)(base + (size_t)(q0 + row) * 1536 + dq);
        float* qp = qs + row * 68 + dq;
        qp[0] = v.x; qp[1] = v.y; qp[2] = v.z; qp[3] = v.w;
    }
    // load K (transposed half2 pairs) and V (half2) window
    for (int idx = tid; idx < 97 * 16; idx += 256) {
        const int jl = idx >> 4, dq = (idx & 15) * 4;
        const int j = W0 + jl;
        float4 kv = make_float4(0.f, 0.f, 0.f, 0.f);
        float4 vv = make_float4(0.f, 0.f, 0.f, 0.f);
        if (j >= 0 && j < SEQ) {
            kv = *(const float4*)(base + HID + (size_t)j * 1536 + dq);
            vv = *(const float4*)(base + 2 * HID + (size_t)j * 1536 + dq);
        }
        const int d2 = dq >> 1;
        *(uint32_t*)&Ksh[(d2 + 0) * 101 + jl] = pack_h2(kv.x, kv.y);
        *(uint32_t*)&Ksh[(d2 + 1) * 101 + jl] = pack_h2(kv.z, kv.w);
        *(uint32_t*)&Vsh[jl * 68 + dq]     = pack_h2(vv.x, vv.y);
        *(uint32_t*)&Vsh[jl * 68 + dq + 2] = pack_h2(vv.z, vv.w);
    }
    __syncthreads();

    // ---- extras pass: lane el<16 -> (query qqe = el>>1, jj = 32+(el&1)) ----
    float sx;
    {
        const int el = lane & 15;
        const int qqe = el >> 1;
        const int jje = 32 + (el & 1);
        const int ile = w * 8 + qqe;
        const int ie = q0 + ile;
        const bool ve = (dir == 0) ? (ie - 33 + jje >= 0) : (ie + jje < SEQ);
        const int jle = ile + jje;           // <= 96
        const float* qe = qs + ile * 68;
        float s = 0.f;
#pragma unroll 4
        for (int d2 = 0; d2 < 32; d2 += 2) {
            const float4 qv = *(const float4*)(qe + 2 * d2);
            const float2 k0 = __half22float2(Ksh[(d2 + 0) * 101 + jle]);
            const float2 k1 = __half22float2(Ksh[(d2 + 1) * 101 + jle]);
            s += qv.x * k0.x + qv.y * k0.y + qv.z * k1.x + qv.w * k1.y;
        }
        sx = ve ? (s * 0.125f + sbias[jje]) : -1e30f;
    }

#pragma unroll 1
    for (int qq = 0; qq < 8; qq++) {
        const int il = w * 8 + qq;
        const int i = q0 + il;
        const int jj0 = lane;                // 0..31
        const bool v0 = (dir == 0) ? (i - 33 + jj0 >= 0) : (i + jj0 < SEQ);
        const int jl0 = il + jj0;            // <= 94
        float s0 = 0.f;
        const float* qr = qs + il * 68;
#pragma unroll 4
        for (int d2 = 0; d2 < 32; d2 += 2) {
            const float4 qv = *(const float4*)(qr + 2 * d2);
            const float2 k0 = __half22float2(Ksh[(d2 + 0) * 101 + jl0]);
            const float2 k1 = __half22float2(Ksh[(d2 + 1) * 101 + jl0]);
            s0 += qv.x * k0.x + qv.y * k0.y + qv.z * k1.x + qv.w * k1.y;
        }
        s0 = v0 ? (s0 * 0.125f + sbias[jj0]) : -1e30f;

        const float se0 = __shfl_sync(0xffffffffu, sx, 2 * qq);
        const float se1 = __shfl_sync(0xffffffffu, sx, 2 * qq + 1);

        float m = fmaxf(s0, fmaxf(se0, se1));
#pragma unroll
        for (int o = 16; o > 0; o >>= 1) m = fmaxf(m, __shfl_xor_sync(0xffffffffu, m, o));
        const float e0 = __expf(s0 - m);
        const float ee0 = __expf(se0 - m);
        const float ee1 = __expf(se1 - m);
        float den = e0;
#pragma unroll
        for (int o = 16; o > 0; o >>= 1) den += __shfl_xor_sync(0xffffffffu, den, o);
        den += ee0 + ee1;

        float o0 = 0.f, o1 = 0.f;
#pragma unroll 4
        for (int jj = 0; jj < 32; jj++) {
            const float p = __shfl_sync(0xffffffffu, e0, jj);
            const float2 vv = __half22float2(*(const __half2*)&Vsh[(il + jj) * 68 + 2 * lane]);
            o0 += p * vv.x;
            o1 += p * vv.y;
        }
        {
            const float2 v32 = __half22float2(*(const __half2*)&Vsh[(il + 32) * 68 + 2 * lane]);
            const float2 v33 = __half22float2(*(const __half2*)&Vsh[(il + 33) * 68 + 2 * lane]);
            o0 += ee0 * v32.x + ee1 * v33.x;
            o1 += ee0 * v32.y + ee1 * v33.y;
        }
        const float inv = 1.f / den;
        const size_t oi = (size_t)dir * TOK * HID + (size_t)(b * SEQ + i) * HID + h * DK + 2 * lane;
        *(uint32_t*)&g_attn_h[oi] = pack_h2(o0 * inv, o1 * inv);
    }
}

// ---------------- launch ----------------
extern "C" void kernel_launch(void* const* d_in, const int* in_sizes, int n_in,
                              void* d_out, int out_size)
{
    const float* inputs = (const float*)d_in[0];
    const float* qkv_w  = (const float*)d_in[2];
    const float* qkv_b  = (const float*)d_in[3];
    const float* rel    = (const float*)d_in[4];
    const float* hw_w   = (const float*)d_in[5];
    const float* hw_b   = (const float*)d_in[6];
    float* out = (float*)d_out;

    float *qkvp, *st;
    __half *ah, *ath, *yh, *y2h, *wq, *wh;
    cudaGetSymbolAddress((void**)&qkvp, g_qkv);
    cudaGetSymbolAddress((void**)&st,   g_st);
    cudaGetSymbolAddress((void**)&ah,   g_act_h);
    cudaGetSymbolAddress((void**)&ath,  g_attn_h);
    cudaGetSymbolAddress((void**)&yh,   g_yh);
    cudaGetSymbolAddress((void**)&y2h,  g_y2h);
    cudaGetSymbolAddress((void**)&wq,   g_wqkv);
    cudaGetSymbolAddress((void**)&wh,   g_whw);

    cudaFuncSetAttribute(gemm_fused, cudaFuncAttributeMaxDynamicSharedMemorySize, GSMEM);
    cudaFuncSetAttribute(attn_v8, cudaFuncAttributeMaxDynamicSharedMemorySize, ATT_SMEM);

    prep_all<<<10240, 256>>>(qkv_w, hw_w, inputs, wq, wh);

    for (int l = 0; l < 2; l++) {
        const size_t QL = (size_t)l * 2 * 4 * HID * HID;
        const size_t HL = (size_t)l * 2 * 2 * 2 * HID * HID;
        const float* qb = qkv_b + (size_t)l * 2 * 4 * HID;
        const float* hb = hw_b + (size_t)l * 2 * 2 * 2 * HID;

        // QKV: fp32 out (mode 0)
        gemm_fused<<<NCTA, 256, GSMEM>>>(
            ah, wq + QL, qb, qkvp, nullptr, nullptr,
            nullptr, nullptr,
            3 * HID, (size_t)4 * HID * HID, (size_t)4 * HID, (size_t)TOK * 3 * HID, 0, 0, 768);

        attn_v8<<<dim3(SEQ / 64, BATCH * NHEAD, 2), 256, ATT_SMEM>>>(
            rel + (size_t)l * 2 * NHEAD * WIN);

        // out projection: fp16 only (mode 1, C=null)
        gemm_fused<<<NCTA, 256, GSMEM>>>(
            ath, wq + QL + (size_t)3 * HID * HID,
            qb + 3 * HID, nullptr, yh, nullptr, nullptr, nullptr,
            HID, (size_t)4 * HID * HID, (size_t)4 * HID, (size_t)TOK * HID, 1, 0, 256);

        // highway 1 (mode 2): A=yh, gate input yh, write y2h
        gemm_fused<<<NCTA, 256, GSMEM>>>(
            yh, wh + HL, hb, nullptr, y2h, yh,
            nullptr, nullptr,
            2 * HID, (size_t)2 * 2 * HID * HID, (size_t)2 * 2 * HID, 0, 2, 0, 512);

        // highway 2 (mode 3): A=y2h, gate input y2h, residual+state+out+ah
        gemm_fused<<<NCTA, 256, GSMEM>>>(
            y2h, wh + HL + (size_t)2 * HID * HID,
            hb + 2 * HID, nullptr, ah, y2h,
            st, out + (size_t)l * TOK * 2 * HID,
            2 * HID, (size_t)2 * 2 * HID * HID, (size_t)2 * 2 * HID, 0, 3, l > 0 ? 1 : 0, 512);
    }
}